// round 2
// baseline (speedup 1.0000x reference)
#include <cuda_runtime.h>

// FFN_36867999269234: y = LN(x); out = x + W2·relu(W1·y + b1) + b2
// H=16, D_MLP=64, tokens = B*T = 1,048,576.
// Strategy: fully fused, one thread per token, packed f32x2 FMA (2x fp32 rate).

#define LN_EPS 1e-5f
#define H 16
#define DM 64

__device__ __forceinline__ unsigned long long pk2(float a, float b) {
    unsigned long long r;
    asm("mov.b64 %0, {%1, %2};" : "=l"(r) : "f"(a), "f"(b));
    return r;
}
__device__ __forceinline__ void upk2(unsigned long long v, float& a, float& b) {
    asm("mov.b64 {%0, %1}, %2;" : "=f"(a), "=f"(b) : "l"(v));
}
__device__ __forceinline__ unsigned long long ffma2(unsigned long long a,
                                                    unsigned long long b,
                                                    unsigned long long c) {
    unsigned long long r;
    asm("fma.rn.f32x2 %0, %1, %2, %3;" : "=l"(r) : "l"(a), "l"(b), "l"(c));
    return r;
}

__global__ __launch_bounds__(256) void ffn_kernel(
    const float* __restrict__ x,
    const float* __restrict__ gamma,
    const float* __restrict__ beta,
    const float* __restrict__ w1,   // [DM, H] row-major
    const float* __restrict__ b1,   // [DM]
    const float* __restrict__ w2,   // [H, DM] row-major
    const float* __restrict__ b2,   // [H]
    float* __restrict__ out,
    int ntok)
{
    // w1s[d][k] = w1[d][k] * gamma[k]   (gamma folded into W1)
    // w2s[d][i] = w2[i][d]              (transposed for contiguous fc2 pairs)
    // b1s[d]    = b1[d] + sum_k w1[d][k]*beta[k]  (beta folded into b1)
    __shared__ __align__(16) float w1s[DM][H];
    __shared__ __align__(16) float w2s[DM][H];
    __shared__ float b1s[DM];
    __shared__ float b2s[H];

    const int tid = threadIdx.x;

    for (int idx = tid; idx < DM * H; idx += 256) {
        int d = idx >> 4;
        int k = idx & 15;
        w1s[d][k] = w1[idx] * gamma[k];
        w2s[d][k] = w2[k * DM + d];
    }
    if (tid < DM) {
        float acc = b1[tid];
        #pragma unroll
        for (int k = 0; k < H; k++) acc = fmaf(w1[tid * H + k], beta[k], acc);
        b1s[tid] = acc;
    }
    if (tid < H) b2s[tid] = b2[tid];
    __syncthreads();

    const long long stride = (long long)gridDim.x * blockDim.x;
    for (long long t = (long long)blockIdx.x * blockDim.x + tid; t < ntok; t += stride) {
        // ---- load token (16 floats, 4x float4) ----
        const float4* xp = (const float4*)(x + t * H);
        float xv[H];
        *(float4*)(xv + 0)  = xp[0];
        *(float4*)(xv + 4)  = xp[1];
        *(float4*)(xv + 8)  = xp[2];
        *(float4*)(xv + 12) = xp[3];

        // ---- LayerNorm (gamma/beta already folded into weights) ----
        float s = 0.f, ss = 0.f;
        #pragma unroll
        for (int k = 0; k < H; k++) { s += xv[k]; ss = fmaf(xv[k], xv[k], ss); }
        const float m = s * (1.f / H);
        const float var = ss * (1.f / H) - m * m;
        const float r = rsqrtf(var + LN_EPS);

        unsigned long long yp[H / 2];
        #pragma unroll
        for (int j = 0; j < H / 2; j++)
            yp[j] = pk2((xv[2 * j] - m) * r, (xv[2 * j + 1] - m) * r);

        // ---- output accumulators start at b2 ----
        unsigned long long op[H / 2];
        #pragma unroll
        for (int j = 0; j < H / 2; j++)
            op[j] = pk2(b2s[2 * j], b2s[2 * j + 1]);

        // ---- fused fc1 -> relu -> fc2 rank-1 update ----
        #pragma unroll 8
        for (int d = 0; d < DM; d++) {
            const ulonglong2* w1q = (const ulonglong2*)w1s[d];  // 4x LDS.128
            const ulonglong2* w2q = (const ulonglong2*)w2s[d];

            // fc1 dot product: two independent packed accumulator chains
            unsigned long long a0 = pk2(b1s[d], 0.f);
            unsigned long long a1 = pk2(0.f, 0.f);
            #pragma unroll
            for (int jj = 0; jj < 4; jj++) {
                ulonglong2 wv = w1q[jj];
                a0 = ffma2(yp[2 * jj],     wv.x, a0);
                a1 = ffma2(yp[2 * jj + 1], wv.y, a1);
            }
            float h0, h1, h2, h3;
            upk2(a0, h0, h1);
            upk2(a1, h2, h3);
            float hd = (h0 + h2) + (h1 + h3);
            hd = fmaxf(hd, 0.f);

            // fc2: out += hd * w2t[d][:]
            const unsigned long long hp = pk2(hd, hd);
            #pragma unroll
            for (int jj = 0; jj < 4; jj++) {
                ulonglong2 wv = w2q[jj];
                op[2 * jj]     = ffma2(hp, wv.x, op[2 * jj]);
                op[2 * jj + 1] = ffma2(hp, wv.y, op[2 * jj + 1]);
            }
        }

        // ---- residual add + store ----
        float res[H];
        #pragma unroll
        for (int j = 0; j < H / 2; j++) {
            float a, b;
            upk2(op[j], a, b);
            res[2 * j]     = xv[2 * j] + a;
            res[2 * j + 1] = xv[2 * j + 1] + b;
        }
        float4* outp = (float4*)(out + t * H);
        outp[0] = *(float4*)(res + 0);
        outp[1] = *(float4*)(res + 4);
        outp[2] = *(float4*)(res + 8);
        outp[3] = *(float4*)(res + 12);
    }
}

extern "C" void kernel_launch(void* const* d_in, const int* in_sizes, int n_in,
                              void* d_out, int out_size) {
    const float* x     = (const float*)d_in[0];
    const float* gamma = (const float*)d_in[1];
    const float* beta  = (const float*)d_in[2];
    const float* w1    = (const float*)d_in[3];
    const float* b1    = (const float*)d_in[4];
    const float* w2    = (const float*)d_in[5];
    const float* b2    = (const float*)d_in[6];
    float* out         = (float*)d_out;

    const int ntok = in_sizes[0] / H;            // 1,048,576
    const int threads = 256;
    int blocks = (ntok + threads * 4 - 1) / (threads * 4);  // ~4 tokens/thread
    if (blocks < 1) blocks = 1;

    ffn_kernel<<<blocks, threads>>>(x, gamma, beta, w1, b1, w2, b2, out, ntok);
}

// round 3
// speedup vs baseline: 1.4165x; 1.4165x over previous
#include <cuda_runtime.h>

// FFN_36867999269234: y = LN(x); out = x + W2·relu(W1·y + b1) + b2
// H=16, D_MLP=64, tokens = B*T = 1,048,576.
// R2: 2 tokens/thread in inner loop (halves LDS/token, doubles ILP),
//     residual+b2 folded into accumulator init to cut register pressure.

#define LN_EPS 1e-5f
#define H 16
#define DM 64

__device__ __forceinline__ unsigned long long pk2(float a, float b) {
    unsigned long long r;
    asm("mov.b64 %0, {%1, %2};" : "=l"(r) : "f"(a), "f"(b));
    return r;
}
__device__ __forceinline__ void upk2(unsigned long long v, float& a, float& b) {
    asm("mov.b64 {%0, %1}, %2;" : "=f"(a), "=f"(b) : "l"(v));
}
__device__ __forceinline__ unsigned long long ffma2(unsigned long long a,
                                                    unsigned long long b,
                                                    unsigned long long c) {
    unsigned long long r;
    asm("fma.rn.f32x2 %0, %1, %2, %3;" : "=l"(r) : "l"(a), "l"(b), "l"(c));
    return r;
}

__global__ __launch_bounds__(256, 2) void ffn_kernel(
    const float* __restrict__ x,
    const float* __restrict__ gamma,
    const float* __restrict__ beta,
    const float* __restrict__ w1,   // [DM, H] row-major
    const float* __restrict__ b1,   // [DM]
    const float* __restrict__ w2,   // [H, DM] row-major
    const float* __restrict__ b2,   // [H]
    float* __restrict__ out,
    long long npair)                // ntok / 2
{
    // w1s[d][k] = w1[d][k] * gamma[k]   (gamma folded into W1)
    // w2s[d][i] = w2[i][d]              (transposed for contiguous fc2 pairs)
    // b1s[d]    = b1[d] + sum_k w1[d][k]*beta[k]  (beta folded into b1)
    __shared__ __align__(16) float w1s[DM][H];
    __shared__ __align__(16) float w2s[DM][H];
    __shared__ float b1s[DM];
    __shared__ float b2s[H];

    const int tid = threadIdx.x;

    for (int idx = tid; idx < DM * H; idx += 256) {
        int d = idx >> 4;
        int k = idx & 15;
        w1s[d][k] = w1[idx] * gamma[k];
        w2s[d][k] = w2[k * DM + d];
    }
    if (tid < DM) {
        float acc = b1[tid];
        #pragma unroll
        for (int k = 0; k < H; k++) acc = fmaf(w1[tid * H + k], beta[k], acc);
        b1s[tid] = acc;
    }
    if (tid < H) b2s[tid] = b2[tid];
    __syncthreads();

    const long long stride = (long long)gridDim.x * blockDim.x;
    for (long long p = (long long)blockIdx.x * blockDim.x + tid; p < npair; p += stride) {
        const long long t0 = 2 * p;

        // ---- load both tokens (2 x 16 floats, contiguous 128B per thread) ----
        const float4* xp = (const float4*)(x + t0 * H);
        float xa[H], xb[H];
        *(float4*)(xa + 0)  = xp[0];
        *(float4*)(xa + 4)  = xp[1];
        *(float4*)(xa + 8)  = xp[2];
        *(float4*)(xa + 12) = xp[3];
        *(float4*)(xb + 0)  = xp[4];
        *(float4*)(xb + 4)  = xp[5];
        *(float4*)(xb + 8)  = xp[6];
        *(float4*)(xb + 12) = xp[7];

        // ---- LayerNorm both tokens ----
        float sa = 0.f, ssa = 0.f, sb = 0.f, ssb = 0.f;
        #pragma unroll
        for (int k = 0; k < H; k++) {
            sa += xa[k]; ssa = fmaf(xa[k], xa[k], ssa);
            sb += xb[k]; ssb = fmaf(xb[k], xb[k], ssb);
        }
        const float ma = sa * (1.f / H);
        const float mb = sb * (1.f / H);
        const float ra = rsqrtf(ssa * (1.f / H) - ma * ma + LN_EPS);
        const float rb = rsqrtf(ssb * (1.f / H) - mb * mb + LN_EPS);

        unsigned long long ya[H / 2], yb[H / 2];
        unsigned long long oa[H / 2], ob[H / 2];
        #pragma unroll
        for (int j = 0; j < H / 2; j++) {
            ya[j] = pk2((xa[2 * j] - ma) * ra, (xa[2 * j + 1] - ma) * ra);
            yb[j] = pk2((xb[2 * j] - mb) * rb, (xb[2 * j + 1] - mb) * rb);
            // residual + b2 folded into the accumulator init: xa/xb die here
            oa[j] = pk2(xa[2 * j] + b2s[2 * j], xa[2 * j + 1] + b2s[2 * j + 1]);
            ob[j] = pk2(xb[2 * j] + b2s[2 * j], xb[2 * j + 1] + b2s[2 * j + 1]);
        }

        // ---- fused fc1 -> relu -> fc2 rank-1 update, 2 tokens per weight row ----
        #pragma unroll 4
        for (int d = 0; d < DM; d++) {
            const ulonglong2* w1q = (const ulonglong2*)w1s[d];  // 4x LDS.128
            const ulonglong2* w2q = (const ulonglong2*)w2s[d];
            const float bd = b1s[d];

            // fc1 dots: 4 independent packed chains (2 per token)
            unsigned long long a0 = pk2(bd, 0.f), a1 = pk2(0.f, 0.f);
            unsigned long long c0 = pk2(bd, 0.f), c1 = pk2(0.f, 0.f);
            #pragma unroll
            for (int jj = 0; jj < 4; jj++) {
                ulonglong2 wv = w1q[jj];
                a0 = ffma2(ya[2 * jj],     wv.x, a0);
                a1 = ffma2(ya[2 * jj + 1], wv.y, a1);
                c0 = ffma2(yb[2 * jj],     wv.x, c0);
                c1 = ffma2(yb[2 * jj + 1], wv.y, c1);
            }
            float h0, h1, h2, h3;
            upk2(a0, h0, h1); upk2(a1, h2, h3);
            float hda = fmaxf((h0 + h2) + (h1 + h3), 0.f);
            upk2(c0, h0, h1); upk2(c1, h2, h3);
            float hdb = fmaxf((h0 + h2) + (h1 + h3), 0.f);

            const unsigned long long hpa = pk2(hda, hda);
            const unsigned long long hpb = pk2(hdb, hdb);
            #pragma unroll
            for (int jj = 0; jj < 4; jj++) {
                ulonglong2 wv = w2q[jj];
                oa[2 * jj]     = ffma2(hpa, wv.x, oa[2 * jj]);
                oa[2 * jj + 1] = ffma2(hpa, wv.y, oa[2 * jj + 1]);
                ob[2 * jj]     = ffma2(hpb, wv.x, ob[2 * jj]);
                ob[2 * jj + 1] = ffma2(hpb, wv.y, ob[2 * jj + 1]);
            }
        }

        // ---- store both tokens (residual already folded in) ----
        float res[H];
        #pragma unroll
        for (int j = 0; j < H / 2; j++) upk2(oa[j], res[2 * j], res[2 * j + 1]);
        float4* outp = (float4*)(out + t0 * H);
        outp[0] = *(float4*)(res + 0);
        outp[1] = *(float4*)(res + 4);
        outp[2] = *(float4*)(res + 8);
        outp[3] = *(float4*)(res + 12);
        #pragma unroll
        for (int j = 0; j < H / 2; j++) upk2(ob[j], res[2 * j], res[2 * j + 1]);
        outp[4] = *(float4*)(res + 0);
        outp[5] = *(float4*)(res + 4);
        outp[6] = *(float4*)(res + 8);
        outp[7] = *(float4*)(res + 12);
    }
}

extern "C" void kernel_launch(void* const* d_in, const int* in_sizes, int n_in,
                              void* d_out, int out_size) {
    const float* x     = (const float*)d_in[0];
    const float* gamma = (const float*)d_in[1];
    const float* beta  = (const float*)d_in[2];
    const float* w1    = (const float*)d_in[3];
    const float* b1    = (const float*)d_in[4];
    const float* w2    = (const float*)d_in[5];
    const float* b2    = (const float*)d_in[6];
    float* out         = (float*)d_out;

    const long long ntok = (long long)in_sizes[0] / H;   // 1,048,576 (even)
    const long long npair = ntok / 2;
    const int threads = 256;
    // 2 pairs (4 tokens) per thread: 1024 blocks covers 524288 pairs
    int blocks = (int)((npair + threads * 2 - 1) / (threads * 2));
    if (blocks < 1) blocks = 1;

    ffn_kernel<<<blocks, threads>>>(x, gamma, beta, w1, b1, w2, b2, out, npair);
}

// round 5
// speedup vs baseline: 2.2273x; 1.5724x over previous
#include <cuda_runtime.h>
#include <cstdint>

// FFN_36867999269234 via mma.sync (HMMA tf32) — tcgen05 unavailable (harness
// builds compute_103 without the 'a' feature set).
//   y = LN(x); h = relu(y·W1^T + b1); out = x + h·W2^T + b2
// H=16, DM=64. One warp processes 16 tokens per tile:
//   MMA1: [16x16]·[16x64]  (2 kstep x 8 ntile,  m16n8k8 tf32)
//   MMA2: [16x64]·[64x16]  (8 kstep x 2 ntile)
// Weights as register fragments (loaded once). h relayout via per-warp smem.

#define H 16
#define DM 64
#define LN_EPS 1e-5f
#define WSTRIDE 84          // floats per smem row (bank-spread: 84*g%32 distinct)
#define YOFF 64             // y/out region col offset (h uses cols 0..63)

__device__ __forceinline__ uint32_t tf32rna(float f) {
    uint32_t r;
    asm("cvt.rna.tf32.f32 %0, %1;" : "=r"(r) : "f"(f));
    return r;
}

__device__ __forceinline__ void mma_tf32(float* c, const uint32_t* a, const uint32_t* b) {
    asm volatile(
        "mma.sync.aligned.m16n8k8.row.col.f32.tf32.tf32.f32 "
        "{%0,%1,%2,%3}, {%4,%5,%6,%7}, {%8,%9}, {%0,%1,%2,%3};"
        : "+f"(c[0]), "+f"(c[1]), "+f"(c[2]), "+f"(c[3])
        : "r"(a[0]), "r"(a[1]), "r"(a[2]), "r"(a[3]), "r"(b[0]), "r"(b[1]));
}

__global__ __launch_bounds__(256) void ffn_mma(
    const float* __restrict__ x,
    const float* __restrict__ gamma,
    const float* __restrict__ beta,
    const float* __restrict__ w1,   // [DM, H]
    const float* __restrict__ b1,   // [DM]
    const float* __restrict__ w2,   // [H, DM]
    const float* __restrict__ b2,   // [H]
    float* __restrict__ out,
    int ntok)
{
    __shared__ float sbuf[8][16 * WSTRIDE];   // per-warp private staging

    const int tid  = threadIdx.x;
    const int wid  = tid >> 5;
    const int lane = tid & 31;
    const int g = lane >> 2;       // groupID  (row base within fragment)
    const int q = lane & 3;        // threadID in group
    float* buf = sbuf[wid];

    // ================= startup: weight fragments in registers =================
    // MMA1 B frags: B1[k][n] = w1[n][k]*gamma[k], frag (kstep s, ntile j):
    //   b0 = B1[8s+q][8j+g], b1 = B1[8s+q+4][8j+g]
    uint32_t B1[2][8][2];
    #pragma unroll
    for (int s = 0; s < 2; s++)
        #pragma unroll
        for (int j = 0; j < 8; j++) {
            int n = 8 * j + g;
            int k0 = 8 * s + q, k1 = k0 + 4;
            B1[s][j][0] = tf32rna(w1[n * H + k0] * gamma[k0]);
            B1[s][j][1] = tf32rna(w1[n * H + k1] * gamma[k1]);
        }
    // C1 bias init (exact f32): cols 2q, 2q+1 of ntile j (rows share values)
    float C1b[8][2];
    #pragma unroll
    for (int j = 0; j < 8; j++) {
        #pragma unroll
        for (int u = 0; u < 2; u++) {
            int n = 8 * j + 2 * q + u;
            float acc = b1[n];
            #pragma unroll
            for (int k = 0; k < H; k++) acc = fmaf(w1[n * H + k], beta[k], acc);
            C1b[j][u] = acc;
        }
    }
    // MMA2 B frags: B2[k][n] = w2[n][k]
    uint32_t B2[8][2][2];
    #pragma unroll
    for (int s = 0; s < 8; s++)
        #pragma unroll
        for (int j = 0; j < 2; j++) {
            int n = 8 * j + g;
            int k0 = 8 * s + q;
            B2[s][j][0] = tf32rna(w2[n * DM + k0]);
            B2[s][j][1] = tf32rna(w2[n * DM + k0 + 4]);
        }
    float C2b[2][2];
    #pragma unroll
    for (int j = 0; j < 2; j++) {
        C2b[j][0] = b2[8 * j + 2 * q];
        C2b[j][1] = b2[8 * j + 2 * q + 1];
    }

    // ======================= token loop (16 tokens/warp) ======================
    const int ntiles = (ntok + 15) >> 4;
    const int wstep  = gridDim.x * 8;
    const int half   = lane & 1;               // each lane owns half a token
    int wt = blockIdx.x * 8 + wid;

    // prefetch first tile's x
    float4 nx0, nx1;
    {
        int t = wt * 16 + (lane >> 1);
        if (t >= ntok) t = ntok - 1;
        const float4* xp = (const float4*)(x + (long long)t * H + half * 8);
        nx0 = xp[0]; nx1 = xp[1];
    }

    for (; wt < ntiles; wt += wstep) {
        const int t = wt * 16 + (lane >> 1);
        const float4 x0 = nx0, x1 = nx1;

        // ---- LayerNorm (2 lanes per token, one butterfly) ----
        float xs[8] = {x0.x, x0.y, x0.z, x0.w, x1.x, x1.y, x1.z, x1.w};
        float s_ = 0.f, ss_ = 0.f;
        #pragma unroll
        for (int i = 0; i < 8; i++) { s_ += xs[i]; ss_ = fmaf(xs[i], xs[i], ss_); }
        s_  += __shfl_xor_sync(0xFFFFFFFFu, s_, 1);
        ss_ += __shfl_xor_sync(0xFFFFFFFFu, ss_, 1);
        const float m = s_ * (1.f / H);
        const float r = rsqrtf(ss_ * (1.f / H) - m * m + LN_EPS);

        // ---- y (tf32) -> smem, token-row layout at col YOFF ----
        uint32_t yb[8];
        #pragma unroll
        for (int i = 0; i < 8; i++) yb[i] = tf32rna((xs[i] - m) * r);
        {
            uint32_t* row = (uint32_t*)(buf + (lane >> 1) * WSTRIDE + YOFF + half * 8);
            ((uint4*)row)[0] = make_uint4(yb[0], yb[1], yb[2], yb[3]);
            ((uint4*)row)[1] = make_uint4(yb[4], yb[5], yb[6], yb[7]);
        }

        // ---- prefetch next tile's x (covers DRAM latency over mma phases) ----
        {
            int nwt = wt + wstep;
            if (nwt < ntiles) {
                int tn = nwt * 16 + (lane >> 1);
                if (tn >= ntok) tn = ntok - 1;
                const float4* xp = (const float4*)(x + (long long)tn * H + half * 8);
                nx0 = xp[0]; nx1 = xp[1];
            }
        }

        __syncwarp();

        // ---- A1 fragments from y ----
        uint32_t A1[2][4];
        #pragma unroll
        for (int s = 0; s < 2; s++) {
            const float* yb0 = buf + YOFF + 8 * s + q;
            A1[s][0] = __float_as_uint(yb0[g * WSTRIDE]);
            A1[s][1] = __float_as_uint(yb0[(g + 8) * WSTRIDE]);
            A1[s][2] = __float_as_uint(yb0[g * WSTRIDE + 4]);
            A1[s][3] = __float_as_uint(yb0[(g + 8) * WSTRIDE + 4]);
        }

        // ---- MMA1: C1[16x64] = y·W1^T + b1 ----
        float C1[8][4];
        #pragma unroll
        for (int j = 0; j < 8; j++) {
            C1[j][0] = C1b[j][0]; C1[j][1] = C1b[j][1];
            C1[j][2] = C1b[j][0]; C1[j][3] = C1b[j][1];
            mma_tf32(C1[j], A1[0], B1[0][j]);
            mma_tf32(C1[j], A1[1], B1[1][j]);
        }

        // ---- relu + tf32 -> smem h (cols 0..63) ----
        #pragma unroll
        for (int j = 0; j < 8; j++) {
            uint32_t h0 = tf32rna(fmaxf(C1[j][0], 0.f));
            uint32_t h1 = tf32rna(fmaxf(C1[j][1], 0.f));
            uint32_t h2 = tf32rna(fmaxf(C1[j][2], 0.f));
            uint32_t h3 = tf32rna(fmaxf(C1[j][3], 0.f));
            uint32_t* p0 = (uint32_t*)(buf + g * WSTRIDE + 8 * j + 2 * q);
            uint32_t* p1 = (uint32_t*)(buf + (g + 8) * WSTRIDE + 8 * j + 2 * q);
            *(uint2*)p0 = make_uint2(h0, h1);
            *(uint2*)p1 = make_uint2(h2, h3);
        }
        __syncwarp();

        // ---- MMA2: C2[16x16] = h·W2^T + b2 ----
        float C2[2][4];
        #pragma unroll
        for (int j = 0; j < 2; j++) {
            C2[j][0] = C2b[j][0]; C2[j][1] = C2b[j][1];
            C2[j][2] = C2b[j][0]; C2[j][3] = C2b[j][1];
        }
        #pragma unroll
        for (int s = 0; s < 8; s++) {
            uint32_t A2[4];
            const float* hb0 = buf + 8 * s + q;
            A2[0] = __float_as_uint(hb0[g * WSTRIDE]);
            A2[1] = __float_as_uint(hb0[(g + 8) * WSTRIDE]);
            A2[2] = __float_as_uint(hb0[g * WSTRIDE + 4]);
            A2[3] = __float_as_uint(hb0[(g + 8) * WSTRIDE + 4]);
            mma_tf32(C2[0], A2, B2[s][0]);
            mma_tf32(C2[1], A2, B2[s][1]);
        }
        __syncwarp();

        // ---- C2 -> smem out region (col YOFF), reload token-major ----
        #pragma unroll
        for (int j = 0; j < 2; j++) {
            *(float2*)(buf + g * WSTRIDE + YOFF + 8 * j + 2 * q) =
                make_float2(C2[j][0], C2[j][1]);
            *(float2*)(buf + (g + 8) * WSTRIDE + YOFF + 8 * j + 2 * q) =
                make_float2(C2[j][2], C2[j][3]);
        }
        __syncwarp();

        if (t < ntok) {
            const float* row = buf + (lane >> 1) * WSTRIDE + YOFF + half * 8;
            float4 o0 = ((const float4*)row)[0];
            float4 o1 = ((const float4*)row)[1];
            o0.x += x0.x; o0.y += x0.y; o0.z += x0.z; o0.w += x0.w;
            o1.x += x1.x; o1.y += x1.y; o1.z += x1.z; o1.w += x1.w;
            float4* op = (float4*)(out + (long long)t * H + half * 8);
            op[0] = o0; op[1] = o1;
        }
        __syncwarp();   // out region reused as y next iteration
    }
}

extern "C" void kernel_launch(void* const* d_in, const int* in_sizes, int n_in,
                              void* d_out, int out_size) {
    const float* x     = (const float*)d_in[0];
    const float* gamma = (const float*)d_in[1];
    const float* beta  = (const float*)d_in[2];
    const float* w1    = (const float*)d_in[3];
    const float* b1    = (const float*)d_in[4];
    const float* w2    = (const float*)d_in[5];
    const float* b2    = (const float*)d_in[6];
    float* out         = (float*)d_out;

    const int ntok = in_sizes[0] / H;   // 1,048,576
    const int threads = 256;            // 8 warps x 16 tokens = 128 tokens/CTA/iter
    int blocks = 296;                   // grid-stride persistent
    ffn_mma<<<blocks, threads>>>(x, gamma, beta, w1, b1, w2, b2, out, ntok);
}

// round 6
// speedup vs baseline: 4.7128x; 2.1159x over previous
#include <cuda_runtime.h>
#include <cstdint>

// FFN_36867999269234 via mma.sync m16n8k16.f16 (f32 accum).
//   y = LN(x); h = relu(y·W1^T + b1); out = x + h·W2^T + b2
// f16 mantissa == tf32 mantissa (10 bits) -> same accuracy as tf32 path.
// Key trick: m16n8k16 C-fragment {c0,c1}={row g, cols 2q,2q+1} packs directly
// into the A-fragment f16x2 slots -> relu(C1) becomes A2 via cvt only
// (no smem round-trip, no shuffles).
// One warp = 16 tokens/tile. MMA1: 8x mma (K=16). MMA2: 4 ksteps x 2 ntiles.

#define H 16
#define DM 64
#define LN_EPS 1e-5f
#define OSTRIDE 20   // floats per token row in out staging (16B-aligned rows)

__device__ __forceinline__ uint32_t packh2(float lo, float hi) {
    uint32_t r;
    asm("cvt.rn.f16x2.f32 %0, %1, %2;" : "=r"(r) : "f"(hi), "f"(lo));
    return r;
}

__device__ __forceinline__ void mma_f16(float* c, const uint32_t* a, const uint32_t* b) {
    asm volatile(
        "mma.sync.aligned.m16n8k16.row.col.f32.f16.f16.f32 "
        "{%0,%1,%2,%3}, {%4,%5,%6,%7}, {%8,%9}, {%0,%1,%2,%3};"
        : "+f"(c[0]), "+f"(c[1]), "+f"(c[2]), "+f"(c[3])
        : "r"(a[0]), "r"(a[1]), "r"(a[2]), "r"(a[3]), "r"(b[0]), "r"(b[1]));
}

__global__ __launch_bounds__(128, 4) void ffn_mma(
    const float* __restrict__ x,
    const float* __restrict__ gamma,
    const float* __restrict__ beta,
    const float* __restrict__ w1,   // [DM, H]
    const float* __restrict__ b1,   // [DM]
    const float* __restrict__ w2,   // [H, DM]
    const float* __restrict__ b2,   // [H]
    float* __restrict__ out,
    int ntok)
{
    __shared__ uint32_t ybuf_s[4][16 * 8];        // y as f16x2 pairs, per warp
    __shared__ float    obuf_s[4][16 * OSTRIDE];  // out staging, per warp
    __shared__ float    c1bs[8][8];               // folded b1 per (j, col)
    __shared__ float    c2bs[16];                 // b2

    const int tid  = threadIdx.x;
    const int wid  = tid >> 5;
    const int lane = tid & 31;
    const int g = lane >> 2;       // groupID
    const int q = lane & 3;        // thread-in-group
    uint32_t* ybuf = ybuf_s[wid];
    float*    obuf = obuf_s[wid];

    // ---------------- weight fragments (f16x2, registers) ----------------
    // B1[j]: W1g[k][n] = w1[n][k]*gamma[k];  b0={k=2q,2q+1 | n=8j+g}, b1={k=2q+8,2q+9}
    uint32_t B1[8][2];
    #pragma unroll
    for (int j = 0; j < 8; j++) {
        const float* wr = w1 + (8 * j + g) * H;
        B1[j][0] = packh2(wr[2 * q]     * gamma[2 * q],     wr[2 * q + 1] * gamma[2 * q + 1]);
        B1[j][1] = packh2(wr[2 * q + 8] * gamma[2 * q + 8], wr[2 * q + 9] * gamma[2 * q + 9]);
    }
    // B2[s][jn]: B2mat[k][n] = w2[n][k]; kstep s covers k=16s..16s+15
    uint32_t B2[4][2][2];
    #pragma unroll
    for (int s = 0; s < 4; s++)
        #pragma unroll
        for (int jn = 0; jn < 2; jn++) {
            const float* wr = w2 + (8 * jn + g) * DM + 16 * s;
            B2[s][jn][0] = packh2(wr[2 * q],     wr[2 * q + 1]);
            B2[s][jn][1] = packh2(wr[2 * q + 8], wr[2 * q + 9]);
        }

    // ---------------- bias LUTs in shared (saves 20 regs) ----------------
    if (tid < 64) {
        int j = tid >> 3, c = tid & 7, n = 8 * j + c;
        float acc = b1[n];
        #pragma unroll
        for (int k = 0; k < H; k++) acc = fmaf(w1[n * H + k], beta[k], acc);
        c1bs[j][c] = acc;
    }
    if (tid < 16) c2bs[tid] = b2[tid];
    __syncthreads();

    // ---------------- token loop: 16 tokens per warp-tile -----------------
    const int ntiles = (ntok + 15) >> 4;
    const int wstep  = gridDim.x * 4;
    const int tk   = lane >> 1;        // token slot within tile (2 lanes/token)
    const int half = lane & 1;         // which 8 cols this lane owns
    int wt = blockIdx.x * 4 + wid;

    float4 nx0, nx1;
    {
        int t = wt * 16 + tk;
        if (t >= ntok) t = ntok - 1;
        const float4* xp = (const float4*)(x + (long long)t * H + half * 8);
        nx0 = xp[0]; nx1 = xp[1];
    }

    for (; wt < ntiles; wt += wstep) {
        const int t = wt * 16 + tk;
        const float4 x0 = nx0, x1 = nx1;

        // ---- LayerNorm (2 lanes per token, one butterfly) ----
        float xs[8] = {x0.x, x0.y, x0.z, x0.w, x1.x, x1.y, x1.z, x1.w};
        float s_ = 0.f, ss_ = 0.f;
        #pragma unroll
        for (int i = 0; i < 8; i++) { s_ += xs[i]; ss_ = fmaf(xs[i], xs[i], ss_); }
        s_  += __shfl_xor_sync(0xFFFFFFFFu, s_, 1);
        ss_ += __shfl_xor_sync(0xFFFFFFFFu, ss_, 1);
        const float m = s_ * (1.f / H);
        const float r = rsqrtf(ss_ * (1.f / H) - m * m + LN_EPS);

        // ---- y -> f16x2 pairs -> smem (one STS.128 per lane) ----
        uint32_t yh[4];
        #pragma unroll
        for (int i = 0; i < 4; i++)
            yh[i] = packh2((xs[2 * i] - m) * r, (xs[2 * i + 1] - m) * r);
        *(uint4*)(ybuf + tk * 8 + half * 4) = make_uint4(yh[0], yh[1], yh[2], yh[3]);
        __syncwarp();

        // ---- A1 fragment (pairs q, q+4 of token rows g, g+8) ----
        uint32_t A1[4];
        A1[0] = ybuf[g * 8 + q];
        A1[1] = ybuf[(g + 8) * 8 + q];
        A1[2] = ybuf[g * 8 + q + 4];
        A1[3] = ybuf[(g + 8) * 8 + q + 4];

        // ---- prefetch next tile's x ----
        {
            int nwt = wt + wstep;
            if (nwt < ntiles) {
                int tn = nwt * 16 + tk;
                if (tn >= ntok) tn = ntok - 1;
                const float4* xp = (const float4*)(x + (long long)tn * H + half * 8);
                nx0 = xp[0]; nx1 = xp[1];
            }
        }

        // ---- MMA1: C1[16x64] = y·W1^T + b1 (8 n-tiles, one K=16 step) ----
        float C1[8][4];
        #pragma unroll
        for (int j = 0; j < 8; j++) {
            const float bl = c1bs[j][2 * q], bh = c1bs[j][2 * q + 1];
            C1[j][0] = bl; C1[j][1] = bh; C1[j][2] = bl; C1[j][3] = bh;
            mma_f16(C1[j], A1, B1[j]);
        }

        // ---- MMA2: C2[16x16] = relu(h)·W2^T + b2 ----
        // relu(C1) -> A2 directly: C frag {c0,c1} == A frag f16x2 slot layout.
        float C2[2][4];
        #pragma unroll
        for (int jn = 0; jn < 2; jn++) {
            const float bl = c2bs[8 * jn + 2 * q], bh = c2bs[8 * jn + 2 * q + 1];
            C2[jn][0] = bl; C2[jn][1] = bh; C2[jn][2] = bl; C2[jn][3] = bh;
        }
        #pragma unroll
        for (int s = 0; s < 4; s++) {
            uint32_t A2[4];
            A2[0] = packh2(fmaxf(C1[2 * s][0], 0.f),     fmaxf(C1[2 * s][1], 0.f));
            A2[1] = packh2(fmaxf(C1[2 * s][2], 0.f),     fmaxf(C1[2 * s][3], 0.f));
            A2[2] = packh2(fmaxf(C1[2 * s + 1][0], 0.f), fmaxf(C1[2 * s + 1][1], 0.f));
            A2[3] = packh2(fmaxf(C1[2 * s + 1][2], 0.f), fmaxf(C1[2 * s + 1][3], 0.f));
            mma_f16(C2[0], A2, B2[s][0]);
            mma_f16(C2[1], A2, B2[s][1]);
        }

        // ---- C2 -> staging (token-major), residual add, store ----
        #pragma unroll
        for (int jn = 0; jn < 2; jn++) {
            *(float2*)(obuf + g * OSTRIDE + 8 * jn + 2 * q) =
                make_float2(C2[jn][0], C2[jn][1]);
            *(float2*)(obuf + (g + 8) * OSTRIDE + 8 * jn + 2 * q) =
                make_float2(C2[jn][2], C2[jn][3]);
        }
        __syncwarp();

        if (t < ntok) {
            const float* row = obuf + tk * OSTRIDE + half * 8;
            float4 o0 = ((const float4*)row)[0];
            float4 o1 = ((const float4*)row)[1];
            o0.x += x0.x; o0.y += x0.y; o0.z += x0.z; o0.w += x0.w;
            o1.x += x1.x; o1.y += x1.y; o1.z += x1.z; o1.w += x1.w;
            float4* op = (float4*)(out + (long long)t * H + half * 8);
            op[0] = o0; op[1] = o1;
        }
        __syncwarp();   // obuf/ybuf reuse guard for next iteration
    }
}

extern "C" void kernel_launch(void* const* d_in, const int* in_sizes, int n_in,
                              void* d_out, int out_size) {
    const float* x     = (const float*)d_in[0];
    const float* gamma = (const float*)d_in[1];
    const float* beta  = (const float*)d_in[2];
    const float* w1    = (const float*)d_in[3];
    const float* b1    = (const float*)d_in[4];
    const float* w2    = (const float*)d_in[5];
    const float* b2    = (const float*)d_in[6];
    float* out         = (float*)d_out;

    const int ntok = in_sizes[0] / H;   // 1,048,576
    const int threads = 128;            // 4 warps x 16 tokens = 64 tokens/CTA/iter
    int blocks = 148 * 4;               // persistent grid-stride, 4 CTAs/SM target
    ffn_mma<<<blocks, threads>>>(x, gamma, beta, w1, b1, w2, b2, out, ntok);
}